// round 14
// baseline (speedup 1.0000x reference)
#include <cuda_runtime.h>
#include <cuda_fp16.h>
#include <cstdint>
#include <math.h>

#define Bn 256
#define Sn 512
#define Hn 64
#define En 330
#define Tn 16
#define Gn 256   // 4H
#define START_IX 14
#define STOP_IX 15
#define NROWS_TOTAL 20868
#define NPAIRS 165   // En/2 k-pairs across the concatenated segments

// ---- scratch (static device memory) ----
__device__ __align__(16) __half2 g_WT2[NPAIRS * 512];  // paired Wih^T fp16: (w_{2p}, w_{2p+1}) at col j
__device__ float g_bias[512];
__device__ __align__(16) __half g_proj[(size_t)NROWS_TOTAL * 512];  // projected tables ~21.4MB (fp16)
__device__ __align__(16) __half g_xp[2][(size_t)Sn * Bn * Gn];      // x-projections  2x67MB (fp16)
__device__ __align__(16) __half g_h[2][(size_t)Sn * Bn * Hn];       // lstm hidden    2x16.8MB (fp16)
__device__ float g_feats[(size_t)Sn * Bn * Tn];        // emissions         8.4MB

// ---- packed f32x2 helpers ----
__device__ __forceinline__ void fma2(unsigned long long& d, unsigned long long a,
                                     unsigned long long b) {
    asm("fma.rn.f32x2 %0, %1, %2, %0;" : "+l"(d) : "l"(a), "l"(b));
}
__device__ __forceinline__ unsigned long long pack2(float a, float b) {
    unsigned long long v;
    asm("mov.b64 %0, {%1,%2};" : "=l"(v) : "f"(a), "f"(b));
    return v;
}
__device__ __forceinline__ float2 unpack2(unsigned long long v) {
    float2 r;
    asm("mov.b64 {%0,%1}, %2;" : "=f"(r.x), "=f"(r.y) : "l"(v));
    return r;
}
__device__ __forceinline__ float tanhfast(float x) {
    float y;
    asm("tanh.approx.f32 %0, %1;" : "=f"(y) : "f"(x));
    return y;
}
__device__ __forceinline__ float sigfast(float x) {
    return fmaf(0.5f, tanhfast(0.5f * x), 0.5f);
}
// load 4 consecutive halves as float4 (8B vector load)
__device__ __forceinline__ float4 ld4h(const __half* p) {
    uint2 u = *(const uint2*)p;
    __half2 h0 = *reinterpret_cast<__half2*>(&u.x);
    __half2 h1 = *reinterpret_cast<__half2*>(&u.y);
    float2 a = __half22float2(h0), b = __half22float2(h1);
    return make_float4(a.x, a.y, b.x, b.y);
}
// store float4 as 4 consecutive halves (8B vector store)
__device__ __forceinline__ void st4h(__half* p, float4 v) {
    __half2 h0 = __floats2half2_rn(v.x, v.y);
    __half2 h1 = __floats2half2_rn(v.z, v.w);
    uint2 u;
    u.x = *reinterpret_cast<unsigned*>(&h0);
    u.y = *reinterpret_cast<unsigned*>(&h1);
    *(uint2*)p = u;
}

// ---- K0: build paired fp16 WT (k-pairs) and fold biases ----
// idx over NPAIRS*512: p = k-pair index in concatenated E-dim, j = output col.
__global__ void prep_kernel(const float* __restrict__ Wf, const float* __restrict__ Wb,
                            const float* __restrict__ bihf, const float* __restrict__ bhhf,
                            const float* __restrict__ bihb, const float* __restrict__ bhhb) {
    int idx = blockIdx.x * blockDim.x + threadIdx.x;
    if (idx < NPAIRS * 512) {
        int p = idx / 512, j = idx % 512;
        int c0 = 2 * p, c1 = 2 * p + 1;    // rows in concatenated E
        float w0, w1;
        if (j < 256) { w0 = Wf[j * En + c0]; w1 = Wf[j * En + c1]; }
        else         { w0 = Wb[(j - 256) * En + c0]; w1 = Wb[(j - 256) * En + c1]; }
        g_WT2[idx] = __floats2half2_rn(w0, w1);
    }
    if (idx < 512) {
        g_bias[idx] = (idx < 256) ? (bihf[idx] + bhhf[idx]) : (bihb[idx - 256] + bhhb[idx - 256]);
    }
}

// ---- K1: project ALL embedding tables into g_proj (fp16 out), 8 rows/block ----
// segpair offsets (in k-pairs): word 0, flag 50, bound 75, radical 100, pinyin 125
__global__ __launch_bounds__(512)
void proj_all_kernel(const float* __restrict__ word, const float* __restrict__ flag,
                     const float* __restrict__ bound, const float* __restrict__ radical,
                     const float* __restrict__ pinyin) {
    const int bb = blockIdx.x;
    const float* emb;
    int nrows, width, segpair, base, r0;
    if (bb < 2500)      { emb = word;    nrows = 20000; width = 100; segpair = 0;   base = 0;     r0 = bb * 8; }
    else if (bb < 2508) { emb = flag;    nrows = 60;    width = 50;  segpair = 50;  base = 20000; r0 = (bb - 2500) * 8; }
    else if (bb < 2509) { emb = bound;   nrows = 8;     width = 50;  segpair = 75;  base = 20060; r0 = 0; }
    else if (bb < 2547) { emb = radical; nrows = 300;   width = 50;  segpair = 100; base = 20068; r0 = (bb - 2509) * 8; }
    else                { emb = pinyin;  nrows = 500;   width = 80;  segpair = 125; base = 20368; r0 = (bb - 2547) * 8; }

    const int j = threadIdx.x;             // output column 0..511
    __shared__ __align__(16) float es[8][112];
    for (int i = threadIdx.x; i < 8 * width; i += 512) {
        int rr = i / width, kk = i % width;
        es[rr][kk] = (r0 + rr < nrows) ? emb[(size_t)(r0 + rr) * width + kk] : 0.f;
    }
    __syncthreads();

    unsigned long long acc[8] = {0ull, 0ull, 0ull, 0ull, 0ull, 0ull, 0ull, 0ull};
    const int hw = width >> 1;
    for (int kk = 0; kk < hw; kk++) {
        __half2 wh = g_WT2[(size_t)(segpair + kk) * 512 + j];
        float2 wf = __half22float2(wh);
        unsigned long long w2 = pack2(wf.x, wf.y);
#pragma unroll
        for (int r = 0; r < 8; r++) {
            unsigned long long h2 = *(const unsigned long long*)&es[r][2 * kk];
            fma2(acc[r], h2, w2);
        }
    }
#pragma unroll
    for (int r = 0; r < 8; r++) {
        if (r0 + r < nrows) {
            float2 u = unpack2(acc[r]);
            g_proj[(size_t)(base + r0 + r) * 512 + j] = __float2half(u.x + u.y);
        }
    }
}

// ---- K2: gather-sum fp16 tables -> fp16 xp, fp32 accumulate, 8 pos/block ----
__global__ __launch_bounds__(128)
void gather_kernel(const int* __restrict__ wi, const int* __restrict__ fi,
                   const int* __restrict__ bi, const int* __restrict__ ri,
                   const int* __restrict__ pi) {
    const int t = threadIdx.x;             // 0..127, each handles 4 columns
    const float4 bias4 = *(const float4*)(g_bias + 4 * t);
#pragma unroll
    for (int pos = 0; pos < 8; pos++) {
        const int sb = blockIdx.x * 8 + pos;   // sb = s*B + b
        const int s = sb >> 8, b = sb & 255;
        const int iw  = wi[b * Sn + s];
        const int ifl = fi[b * Sn + s];
        const int ib  = bi[b * Sn + s];
        const int ir  = ri[b * Sn + s];
        const int ip  = pi[b * Sn + s];
        float4 a0 = ld4h(g_proj + (size_t)iw * 512 + 4 * t);
        float4 a1 = ld4h(g_proj + (size_t)(20000 + ifl) * 512 + 4 * t);
        float4 a2 = ld4h(g_proj + (size_t)(20060 + ib) * 512 + 4 * t);
        float4 a3 = ld4h(g_proj + (size_t)(20068 + ir) * 512 + 4 * t);
        float4 a4 = ld4h(g_proj + (size_t)(20368 + ip) * 512 + 4 * t);
        float4 v = bias4;
        v.x += a0.x + a1.x + a2.x + a3.x + a4.x;
        v.y += a0.y + a1.y + a2.y + a3.y + a4.y;
        v.z += a0.z + a1.z + a2.z + a3.z + a4.z;
        v.w += a0.w + a1.w + a2.w + a3.w + a4.w;
        if (t < 64) st4h(g_xp[0] + (size_t)sb * Gn + 4 * t, v);
        else        st4h(g_xp[1] + (size_t)sb * Gn + 4 * t - 256, v);
    }
}

// ---- K3: recurrence. grid (128,2)=256 CTAs, 256 thr, Bc=2, 2 CTAs/SM ----
__global__ __launch_bounds__(256, 2)
void lstm_kernel(const float* __restrict__ Whh_f, const float* __restrict__ Whh_b,
                 const float* __restrict__ h0, const float* __restrict__ c0) {
    const int dir = blockIdx.y;
    const int b0 = blockIdx.x * 2;
    const float* __restrict__ Whh = dir ? Whh_b : Whh_f;
    const __half* __restrict__ xp = g_xp[dir];
    __half* __restrict__ hout = g_h[dir];
    const int j = threadIdx.x;             // gate-output index 0..255

    unsigned long long wp[32];
    {
        const ulonglong2* wrow = (const ulonglong2*)(Whh + j * 64);
#pragma unroll
        for (int q = 0; q < 16; q++) { ulonglong2 t2 = wrow[q]; wp[2 * q] = t2.x; wp[2 * q + 1] = t2.y; }
    }

    __shared__ __align__(16) float h_sh[2][64];
    __shared__ float z_sh[2][256];

    const int cb = (j >> 6) & 1, ck = j & 63;
    float c = 0.f;
    if (j < 128) {
        c = c0[dir * Bn * Hn + (b0 + cb) * Hn + ck];
        h_sh[cb][ck] = h0[dir * Bn * Hn + (b0 + cb) * Hn + ck];
    }

    int t = dir ? (Sn - 1) : 0;
    const __half* xr = xp + ((size_t)t * Bn + b0) * Gn + j;
    float xc0 = __half2float(xr[0]), xc1 = __half2float(xr[Gn]);
    __syncthreads();

    for (int step = 0; step < Sn; step++) {
        float xn0 = 0.f, xn1 = 0.f;
        if (step + 1 < Sn) {
            int tn = dir ? (t - 1) : (t + 1);
            const __half* xn = xp + ((size_t)tn * Bn + b0) * Gn + j;
            xn0 = __half2float(xn[0]); xn1 = __half2float(xn[Gn]);
        }
        unsigned long long acc0 = 0ull, acc1 = 0ull;
        const ulonglong2* h0p = (const ulonglong2*)h_sh[0];
        const ulonglong2* h1p = (const ulonglong2*)h_sh[1];
#pragma unroll
        for (int q = 0; q < 16; q++) {
            ulonglong2 v0 = h0p[q], v1 = h1p[q];
            fma2(acc0, v0.x, wp[2 * q]); fma2(acc0, v0.y, wp[2 * q + 1]);
            fma2(acc1, v1.x, wp[2 * q]); fma2(acc1, v1.y, wp[2 * q + 1]);
        }
        {
            float2 u0 = unpack2(acc0), u1 = unpack2(acc1);
            z_sh[0][j] = xc0 + u0.x + u0.y;
            z_sh[1][j] = xc1 + u1.x + u1.y;
        }
        __syncthreads();

        if (j < 128) {
            float zi = z_sh[cb][ck];
            float zf = z_sh[cb][64 + ck];
            float zg = z_sh[cb][128 + ck];
            float zo = z_sh[cb][192 + ck];
            c = sigfast(zf) * c + sigfast(zi) * tanhfast(zg);
            float hh = sigfast(zo) * tanhfast(c);
            h_sh[cb][ck] = hh;
            hout[((size_t)t * Bn + b0 + cb) * Hn + ck] = __float2half(hh);
        }
        __syncthreads();

        xc0 = xn0; xc1 = xn1;
        t = dir ? (t - 1) : (t + 1);
    }
}

// ---- K4: emissions from fp16 h; 128 positions per block (4 tiles of 32),
//      Wout staged once per block ----
__global__ __launch_bounds__(512)
void feats_kernel(const float* __restrict__ Wout, const float* __restrict__ bout) {
    const int tid = threadIdx.x;
    __shared__ __align__(16) float hs[32][132];
    __shared__ __align__(16) float ws[16 * 132];
    __shared__ float bs[16];

    {
        int f = tid * 4;
        if (f < 2048) {
            float4 w4 = *(const float4*)(Wout + f);
            int row = f >> 7, off = f & 127;
            *(float4*)&ws[row * 132 + off] = w4;
        }
        if (tid < 16) bs[tid] = bout[tid];
    }

#pragma unroll
    for (int tile = 0; tile < 4; tile++) {
        const int p0 = blockIdx.x * 128 + tile * 32;
        __syncthreads();   // ws ready (tile 0) / previous tile's reads done
        {
            int f = tid * 4;
            float4 hf4 = ld4h(g_h[0] + (size_t)p0 * Hn + f);
            float4 hb4 = ld4h(g_h[1] + (size_t)p0 * Hn + f);
            int pos = f >> 6, off = f & 63;
            *(float4*)&hs[pos][off] = hf4;
            *(float4*)&hs[pos][64 + off] = hb4;
        }
        __syncthreads();

        const int pos = tid >> 4, tag = tid & 15;
        const float4* hv = (const float4*)&hs[pos][0];
        const float4* wv = (const float4*)&ws[tag * 132];
        float acc0 = bs[tag], acc1 = 0.f;
#pragma unroll
        for (int kq = 0; kq < 32; kq += 2) {
            float4 a = hv[kq], b = wv[kq];
            float4 a2 = hv[kq + 1], b2 = wv[kq + 1];
            acc0 = fmaf(a.x, b.x, fmaf(a.y, b.y, acc0));
            acc1 = fmaf(a.z, b.z, fmaf(a.w, b.w, acc1));
            acc0 = fmaf(a2.x, b2.x, fmaf(a2.y, b2.y, acc0));
            acc1 = fmaf(a2.z, b2.z, fmaf(a2.w, b2.w, acc1));
        }
        g_feats[(size_t)(p0 + pos) * Tn + tag] = acc0 + acc1;
    }
}

// ---- K5: CRF forward + real path -> loss. 3-deep feat prefetch ----
__global__ __launch_bounds__(32)
void crf_kernel(const float* __restrict__ transitions,
                const int* __restrict__ tags, float* __restrict__ out) {
    const int b = blockIdx.x * 2 + (threadIdx.x >> 4);
    const int n = threadIdx.x & 15;        // "next" tag this lane owns
    const unsigned FULL = 0xFFFFFFFFu;

    float expT[16];
#pragma unroll
    for (int k = 0; k < 16; k++) expT[k] = __expf(transitions[n * 16 + k]);

    // step 0 analytic: alpha = feats[0] + T[n, START]  (exact in fp32)
    float alpha = g_feats[(size_t)b * Tn + n] + transitions[n * 16 + START_IX];
    // 3-deep pipeline of feat loads (feat for s = 1, 2, 3)
    float fA = g_feats[((size_t)1 * Bn + b) * Tn + n];
    float fB = g_feats[((size_t)2 * Bn + b) * Tn + n];
    float fC = g_feats[((size_t)3 * Bn + b) * Tn + n];

    for (int s = 1; s < Sn; s++) {
        float fD = 0.f;
        if (s + 3 < Sn) fD = g_feats[((size_t)(s + 3) * Bn + b) * Tn + n];
        float m = __shfl_sync(FULL, alpha, 0, 16);
        float e = __expf(alpha - m);
        float acc_a = 0.f, acc_b = 0.f;
#pragma unroll
        for (int k = 0; k < 16; k += 2) {
            acc_a = fmaf(__shfl_sync(FULL, e, k, 16), expT[k], acc_a);
            acc_b = fmaf(__shfl_sync(FULL, e, k + 1, 16), expT[k + 1], acc_b);
        }
        alpha = fA + m + __logf(acc_a + acc_b);
        fA = fB; fB = fC; fC = fD;
    }
    float v = alpha + transitions[STOP_IX * 16 + n];
    float m2 = v;
#pragma unroll
    for (int o = 8; o; o >>= 1) m2 = fmaxf(m2, __shfl_xor_sync(FULL, m2, o, 16));
    float se = __expf(v - m2);
#pragma unroll
    for (int o = 8; o; o >>= 1) se += __shfl_xor_sync(FULL, se, o, 16);
    float all_sc = m2 + __logf(se);

    float rp = 0.f;
    for (int s = n; s < Sn; s += 16) {
        int tg = tags[b * Sn + s];
        int pv = (s == 0) ? START_IX : tags[b * Sn + s - 1];
        rp += g_feats[((size_t)s * Bn + b) * Tn + tg] + transitions[tg * 16 + pv];
    }
#pragma unroll
    for (int o = 8; o; o >>= 1) rp += __shfl_xor_sync(FULL, rp, o, 16);

    if (n == 0) {
        float real = rp + transitions[STOP_IX * 16 + tags[b * Sn + Sn - 1]];
        out[b] = all_sc - real;
    }
}

extern "C" void kernel_launch(void* const* d_in, const int* in_sizes, int n_in,
                              void* d_out, int out_size) {
    const float* word_emb    = (const float*)d_in[0];
    const float* flag_emb    = (const float*)d_in[1];
    const float* bound_emb   = (const float*)d_in[2];
    const float* radical_emb = (const float*)d_in[3];
    const float* pinyin_emb  = (const float*)d_in[4];
    const float* Wih_f = (const float*)d_in[5];
    const float* Whh_f = (const float*)d_in[6];
    const float* bih_f = (const float*)d_in[7];
    const float* bhh_f = (const float*)d_in[8];
    const float* Wih_b = (const float*)d_in[9];
    const float* Whh_b = (const float*)d_in[10];
    const float* bih_b = (const float*)d_in[11];
    const float* bhh_b = (const float*)d_in[12];
    const float* Wout  = (const float*)d_in[13];
    const float* bout  = (const float*)d_in[14];
    const float* transitions = (const float*)d_in[15];
    const float* h0 = (const float*)d_in[16];
    const float* c0 = (const float*)d_in[17];
    const int* word_ids    = (const int*)d_in[18];
    const int* flag_ids    = (const int*)d_in[19];
    const int* bound_ids   = (const int*)d_in[20];
    const int* radical_ids = (const int*)d_in[21];
    const int* pinyin_ids  = (const int*)d_in[22];
    const int* tags        = (const int*)d_in[23];

    prep_kernel<<<(NPAIRS * 512 + 255) / 256, 256>>>(Wih_f, Wih_b, bih_f, bhh_f, bih_b, bhh_b);

    proj_all_kernel<<<2610, 512>>>(word_emb, flag_emb, bound_emb, radical_emb, pinyin_emb);

    gather_kernel<<<Sn * Bn / 8, 128>>>(word_ids, flag_ids, bound_ids, radical_ids, pinyin_ids);

    dim3 lgrid(128, 2);
    lstm_kernel<<<lgrid, 256>>>(Whh_f, Whh_b, h0, c0);

    feats_kernel<<<Sn * Bn / 128, 512>>>(Wout, bout);

    crf_kernel<<<Bn / 2, 32>>>(transitions, tags, (float*)d_out);
}

// round 15
// speedup vs baseline: 1.0188x; 1.0188x over previous
#include <cuda_runtime.h>
#include <cuda_fp16.h>
#include <cstdint>
#include <math.h>

#define Bn 256
#define Sn 512
#define Hn 64
#define En 330
#define Tn 16
#define Gn 256   // 4H
#define START_IX 14
#define STOP_IX 15
#define NROWS_TOTAL 20868
#define NPAIRS 165   // En/2 k-pairs across the concatenated segments

// ---- scratch (static device memory) ----
__device__ __align__(16) __half2 g_WT2[NPAIRS * 512];  // paired Wih^T fp16: (w_{2p}, w_{2p+1}) at col j
__device__ float g_bias[512];
__device__ __align__(16) __half g_proj[(size_t)NROWS_TOTAL * 512];  // projected tables ~21.4MB (fp16)
__device__ __align__(16) __half g_xp[2][(size_t)Sn * Bn * Gn];      // x-projections  2x67MB (fp16)
__device__ __align__(16) __half g_h[2][(size_t)Sn * Bn * Hn];       // lstm hidden    2x16.8MB (fp16)
__device__ float g_feats[(size_t)Sn * Bn * Tn];        // emissions         8.4MB

// ---- packed f32x2 helpers ----
__device__ __forceinline__ void fma2(unsigned long long& d, unsigned long long a,
                                     unsigned long long b) {
    asm("fma.rn.f32x2 %0, %1, %2, %0;" : "+l"(d) : "l"(a), "l"(b));
}
__device__ __forceinline__ unsigned long long pack2(float a, float b) {
    unsigned long long v;
    asm("mov.b64 %0, {%1,%2};" : "=l"(v) : "f"(a), "f"(b));
    return v;
}
__device__ __forceinline__ float2 unpack2(unsigned long long v) {
    float2 r;
    asm("mov.b64 {%0,%1}, %2;" : "=f"(r.x), "=f"(r.y) : "l"(v));
    return r;
}
__device__ __forceinline__ float tanhfast(float x) {
    float y;
    asm("tanh.approx.f32 %0, %1;" : "=f"(y) : "f"(x));
    return y;
}
__device__ __forceinline__ float sigfast(float x) {
    return fmaf(0.5f, tanhfast(0.5f * x), 0.5f);
}
// load 4 consecutive halves as float4 (8B vector load)
__device__ __forceinline__ float4 ld4h(const __half* p) {
    uint2 u = *(const uint2*)p;
    __half2 h0 = *reinterpret_cast<__half2*>(&u.x);
    __half2 h1 = *reinterpret_cast<__half2*>(&u.y);
    float2 a = __half22float2(h0), b = __half22float2(h1);
    return make_float4(a.x, a.y, b.x, b.y);
}
// store float4 as 4 consecutive halves (8B vector store)
__device__ __forceinline__ void st4h(__half* p, float4 v) {
    __half2 h0 = __floats2half2_rn(v.x, v.y);
    __half2 h1 = __floats2half2_rn(v.z, v.w);
    uint2 u;
    u.x = *reinterpret_cast<unsigned*>(&h0);
    u.y = *reinterpret_cast<unsigned*>(&h1);
    *(uint2*)p = u;
}

// ---- K0: build paired fp16 WT (k-pairs) and fold biases ----
__global__ void prep_kernel(const float* __restrict__ Wf, const float* __restrict__ Wb,
                            const float* __restrict__ bihf, const float* __restrict__ bhhf,
                            const float* __restrict__ bihb, const float* __restrict__ bhhb) {
    int idx = blockIdx.x * blockDim.x + threadIdx.x;
    if (idx < NPAIRS * 512) {
        int p = idx / 512, j = idx % 512;
        int c0 = 2 * p, c1 = 2 * p + 1;    // rows in concatenated E
        float w0, w1;
        if (j < 256) { w0 = Wf[j * En + c0]; w1 = Wf[j * En + c1]; }
        else         { w0 = Wb[(j - 256) * En + c0]; w1 = Wb[(j - 256) * En + c1]; }
        g_WT2[idx] = __floats2half2_rn(w0, w1);
    }
    if (idx < 512) {
        g_bias[idx] = (idx < 256) ? (bihf[idx] + bhhf[idx]) : (bihb[idx - 256] + bhhb[idx - 256]);
    }
}

// ---- K1: project ALL embedding tables into g_proj (fp16 out), 8 rows/block ----
// segpair offsets (in k-pairs): word 0, flag 50, bound 75, radical 100, pinyin 125
__global__ __launch_bounds__(512)
void proj_all_kernel(const float* __restrict__ word, const float* __restrict__ flag,
                     const float* __restrict__ bound, const float* __restrict__ radical,
                     const float* __restrict__ pinyin) {
    const int bb = blockIdx.x;
    const float* emb;
    int nrows, width, segpair, base, r0;
    if (bb < 2500)      { emb = word;    nrows = 20000; width = 100; segpair = 0;   base = 0;     r0 = bb * 8; }
    else if (bb < 2508) { emb = flag;    nrows = 60;    width = 50;  segpair = 50;  base = 20000; r0 = (bb - 2500) * 8; }
    else if (bb < 2509) { emb = bound;   nrows = 8;     width = 50;  segpair = 75;  base = 20060; r0 = 0; }
    else if (bb < 2547) { emb = radical; nrows = 300;   width = 50;  segpair = 100; base = 20068; r0 = (bb - 2509) * 8; }
    else                { emb = pinyin;  nrows = 500;   width = 80;  segpair = 125; base = 20368; r0 = (bb - 2547) * 8; }

    const int j = threadIdx.x;             // output column 0..511
    __shared__ __align__(16) float es[8][112];
    for (int i = threadIdx.x; i < 8 * width; i += 512) {
        int rr = i / width, kk = i % width;
        es[rr][kk] = (r0 + rr < nrows) ? emb[(size_t)(r0 + rr) * width + kk] : 0.f;
    }
    __syncthreads();

    unsigned long long acc[8] = {0ull, 0ull, 0ull, 0ull, 0ull, 0ull, 0ull, 0ull};
    const int hw = width >> 1;
    for (int kk = 0; kk < hw; kk++) {
        __half2 wh = g_WT2[(size_t)(segpair + kk) * 512 + j];
        float2 wf = __half22float2(wh);
        unsigned long long w2 = pack2(wf.x, wf.y);
#pragma unroll
        for (int r = 0; r < 8; r++) {
            unsigned long long h2 = *(const unsigned long long*)&es[r][2 * kk];
            fma2(acc[r], h2, w2);
        }
    }
#pragma unroll
    for (int r = 0; r < 8; r++) {
        if (r0 + r < nrows) {
            float2 u = unpack2(acc[r]);
            g_proj[(size_t)(base + r0 + r) * 512 + j] = __float2half(u.x + u.y);
        }
    }
}

// ---- K2: gather-sum fp16 tables -> fp16 xp, fp32 accumulate, 4 pos/block ----
__global__ __launch_bounds__(128)
void gather_kernel(const int* __restrict__ wi, const int* __restrict__ fi,
                   const int* __restrict__ bi, const int* __restrict__ ri,
                   const int* __restrict__ pi) {
    const int t = threadIdx.x;             // 0..127, each handles 4 columns
    const float4 bias4 = *(const float4*)(g_bias + 4 * t);
#pragma unroll
    for (int pos = 0; pos < 4; pos++) {
        const int sb = blockIdx.x * 4 + pos;   // sb = s*B + b
        const int s = sb >> 8, b = sb & 255;
        const int iw  = wi[b * Sn + s];
        const int ifl = fi[b * Sn + s];
        const int ib  = bi[b * Sn + s];
        const int ir  = ri[b * Sn + s];
        const int ip  = pi[b * Sn + s];
        float4 a0 = ld4h(g_proj + (size_t)iw * 512 + 4 * t);
        float4 a1 = ld4h(g_proj + (size_t)(20000 + ifl) * 512 + 4 * t);
        float4 a2 = ld4h(g_proj + (size_t)(20060 + ib) * 512 + 4 * t);
        float4 a3 = ld4h(g_proj + (size_t)(20068 + ir) * 512 + 4 * t);
        float4 a4 = ld4h(g_proj + (size_t)(20368 + ip) * 512 + 4 * t);
        float4 v = bias4;
        v.x += a0.x + a1.x + a2.x + a3.x + a4.x;
        v.y += a0.y + a1.y + a2.y + a3.y + a4.y;
        v.z += a0.z + a1.z + a2.z + a3.z + a4.z;
        v.w += a0.w + a1.w + a2.w + a3.w + a4.w;
        if (t < 64) st4h(g_xp[0] + (size_t)sb * Gn + 4 * t, v);
        else        st4h(g_xp[1] + (size_t)sb * Gn + 4 * t - 256, v);
    }
}

// ---- K3: recurrence. grid (128,2)=256 CTAs, 256 thr, Bc=2, 2 CTAs/SM ----
__global__ __launch_bounds__(256, 2)
void lstm_kernel(const float* __restrict__ Whh_f, const float* __restrict__ Whh_b,
                 const float* __restrict__ h0, const float* __restrict__ c0) {
    const int dir = blockIdx.y;
    const int b0 = blockIdx.x * 2;
    const float* __restrict__ Whh = dir ? Whh_b : Whh_f;
    const __half* __restrict__ xp = g_xp[dir];
    __half* __restrict__ hout = g_h[dir];
    const int j = threadIdx.x;             // gate-output index 0..255

    unsigned long long wp[32];
    {
        const ulonglong2* wrow = (const ulonglong2*)(Whh + j * 64);
#pragma unroll
        for (int q = 0; q < 16; q++) { ulonglong2 t2 = wrow[q]; wp[2 * q] = t2.x; wp[2 * q + 1] = t2.y; }
    }

    __shared__ __align__(16) float h_sh[2][64];
    __shared__ float z_sh[2][256];

    const int cb = (j >> 6) & 1, ck = j & 63;
    float c = 0.f;
    if (j < 128) {
        c = c0[dir * Bn * Hn + (b0 + cb) * Hn + ck];
        h_sh[cb][ck] = h0[dir * Bn * Hn + (b0 + cb) * Hn + ck];
    }

    int t = dir ? (Sn - 1) : 0;
    const __half* xr = xp + ((size_t)t * Bn + b0) * Gn + j;
    float xc0 = __half2float(xr[0]), xc1 = __half2float(xr[Gn]);
    __syncthreads();

    for (int step = 0; step < Sn; step++) {
        float xn0 = 0.f, xn1 = 0.f;
        if (step + 1 < Sn) {
            int tn = dir ? (t - 1) : (t + 1);
            const __half* xn = xp + ((size_t)tn * Bn + b0) * Gn + j;
            xn0 = __half2float(xn[0]); xn1 = __half2float(xn[Gn]);
        }
        unsigned long long acc0 = 0ull, acc1 = 0ull;
        const ulonglong2* h0p = (const ulonglong2*)h_sh[0];
        const ulonglong2* h1p = (const ulonglong2*)h_sh[1];
#pragma unroll
        for (int q = 0; q < 16; q++) {
            ulonglong2 v0 = h0p[q], v1 = h1p[q];
            fma2(acc0, v0.x, wp[2 * q]); fma2(acc0, v0.y, wp[2 * q + 1]);
            fma2(acc1, v1.x, wp[2 * q]); fma2(acc1, v1.y, wp[2 * q + 1]);
        }
        {
            float2 u0 = unpack2(acc0), u1 = unpack2(acc1);
            z_sh[0][j] = xc0 + u0.x + u0.y;
            z_sh[1][j] = xc1 + u1.x + u1.y;
        }
        __syncthreads();

        if (j < 128) {
            float zi = z_sh[cb][ck];
            float zf = z_sh[cb][64 + ck];
            float zg = z_sh[cb][128 + ck];
            float zo = z_sh[cb][192 + ck];
            c = sigfast(zf) * c + sigfast(zi) * tanhfast(zg);
            float hh = sigfast(zo) * tanhfast(c);
            h_sh[cb][ck] = hh;
            hout[((size_t)t * Bn + b0 + cb) * Hn + ck] = __float2half(hh);
        }
        __syncthreads();

        xc0 = xn0; xc1 = xn1;
        t = dir ? (t - 1) : (t + 1);
    }
}

// ---- K4: emissions from fp16 h; 128 positions per block (4 tiles of 32),
//      Wout staged once per block ----
__global__ __launch_bounds__(512)
void feats_kernel(const float* __restrict__ Wout, const float* __restrict__ bout) {
    const int tid = threadIdx.x;
    __shared__ __align__(16) float hs[32][132];
    __shared__ __align__(16) float ws[16 * 132];
    __shared__ float bs[16];

    {
        int f = tid * 4;
        if (f < 2048) {
            float4 w4 = *(const float4*)(Wout + f);
            int row = f >> 7, off = f & 127;
            *(float4*)&ws[row * 132 + off] = w4;
        }
        if (tid < 16) bs[tid] = bout[tid];
    }

#pragma unroll
    for (int tile = 0; tile < 4; tile++) {
        const int p0 = blockIdx.x * 128 + tile * 32;
        __syncthreads();   // ws ready (tile 0) / previous tile's reads done
        {
            int f = tid * 4;
            float4 hf4 = ld4h(g_h[0] + (size_t)p0 * Hn + f);
            float4 hb4 = ld4h(g_h[1] + (size_t)p0 * Hn + f);
            int pos = f >> 6, off = f & 63;
            *(float4*)&hs[pos][off] = hf4;
            *(float4*)&hs[pos][64 + off] = hb4;
        }
        __syncthreads();

        const int pos = tid >> 4, tag = tid & 15;
        const float4* hv = (const float4*)&hs[pos][0];
        const float4* wv = (const float4*)&ws[tag * 132];
        float acc0 = bs[tag], acc1 = 0.f;
#pragma unroll
        for (int kq = 0; kq < 32; kq += 2) {
            float4 a = hv[kq], b = wv[kq];
            float4 a2 = hv[kq + 1], b2 = wv[kq + 1];
            acc0 = fmaf(a.x, b.x, fmaf(a.y, b.y, acc0));
            acc1 = fmaf(a.z, b.z, fmaf(a.w, b.w, acc1));
            acc0 = fmaf(a2.x, b2.x, fmaf(a2.y, b2.y, acc0));
            acc1 = fmaf(a2.z, b2.z, fmaf(a2.w, b2.w, acc1));
        }
        g_feats[(size_t)(p0 + pos) * Tn + tag] = acc0 + acc1;
    }
}

// ---- K5: CRF forward + real path -> loss. 3-deep feat prefetch ----
__global__ __launch_bounds__(32)
void crf_kernel(const float* __restrict__ transitions,
                const int* __restrict__ tags, float* __restrict__ out) {
    const int b = blockIdx.x * 2 + (threadIdx.x >> 4);
    const int n = threadIdx.x & 15;        // "next" tag this lane owns
    const unsigned FULL = 0xFFFFFFFFu;

    float expT[16];
#pragma unroll
    for (int k = 0; k < 16; k++) expT[k] = __expf(transitions[n * 16 + k]);

    // step 0 analytic: alpha = feats[0] + T[n, START]  (exact in fp32)
    float alpha = g_feats[(size_t)b * Tn + n] + transitions[n * 16 + START_IX];
    // 3-deep pipeline of feat loads (feat for s = 1, 2, 3)
    float fA = g_feats[((size_t)1 * Bn + b) * Tn + n];
    float fB = g_feats[((size_t)2 * Bn + b) * Tn + n];
    float fC = g_feats[((size_t)3 * Bn + b) * Tn + n];

    for (int s = 1; s < Sn; s++) {
        float fD = 0.f;
        if (s + 3 < Sn) fD = g_feats[((size_t)(s + 3) * Bn + b) * Tn + n];
        float m = __shfl_sync(FULL, alpha, 0, 16);
        float e = __expf(alpha - m);
        float acc_a = 0.f, acc_b = 0.f;
#pragma unroll
        for (int k = 0; k < 16; k += 2) {
            acc_a = fmaf(__shfl_sync(FULL, e, k, 16), expT[k], acc_a);
            acc_b = fmaf(__shfl_sync(FULL, e, k + 1, 16), expT[k + 1], acc_b);
        }
        alpha = fA + m + __logf(acc_a + acc_b);
        fA = fB; fB = fC; fC = fD;
    }
    float v = alpha + transitions[STOP_IX * 16 + n];
    float m2 = v;
#pragma unroll
    for (int o = 8; o; o >>= 1) m2 = fmaxf(m2, __shfl_xor_sync(FULL, m2, o, 16));
    float se = __expf(v - m2);
#pragma unroll
    for (int o = 8; o; o >>= 1) se += __shfl_xor_sync(FULL, se, o, 16);
    float all_sc = m2 + __logf(se);

    float rp = 0.f;
    for (int s = n; s < Sn; s += 16) {
        int tg = tags[b * Sn + s];
        int pv = (s == 0) ? START_IX : tags[b * Sn + s - 1];
        rp += g_feats[((size_t)s * Bn + b) * Tn + tg] + transitions[tg * 16 + pv];
    }
#pragma unroll
    for (int o = 8; o; o >>= 1) rp += __shfl_xor_sync(FULL, rp, o, 16);

    if (n == 0) {
        float real = rp + transitions[STOP_IX * 16 + tags[b * Sn + Sn - 1]];
        out[b] = all_sc - real;
    }
}

extern "C" void kernel_launch(void* const* d_in, const int* in_sizes, int n_in,
                              void* d_out, int out_size) {
    const float* word_emb    = (const float*)d_in[0];
    const float* flag_emb    = (const float*)d_in[1];
    const float* bound_emb   = (const float*)d_in[2];
    const float* radical_emb = (const float*)d_in[3];
    const float* pinyin_emb  = (const float*)d_in[4];
    const float* Wih_f = (const float*)d_in[5];
    const float* Whh_f = (const float*)d_in[6];
    const float* bih_f = (const float*)d_in[7];
    const float* bhh_f = (const float*)d_in[8];
    const float* Wih_b = (const float*)d_in[9];
    const float* Whh_b = (const float*)d_in[10];
    const float* bih_b = (const float*)d_in[11];
    const float* bhh_b = (const float*)d_in[12];
    const float* Wout  = (const float*)d_in[13];
    const float* bout  = (const float*)d_in[14];
    const float* transitions = (const float*)d_in[15];
    const float* h0 = (const float*)d_in[16];
    const float* c0 = (const float*)d_in[17];
    const int* word_ids    = (const int*)d_in[18];
    const int* flag_ids    = (const int*)d_in[19];
    const int* bound_ids   = (const int*)d_in[20];
    const int* radical_ids = (const int*)d_in[21];
    const int* pinyin_ids  = (const int*)d_in[22];
    const int* tags        = (const int*)d_in[23];

    prep_kernel<<<(NPAIRS * 512 + 255) / 256, 256>>>(Wih_f, Wih_b, bih_f, bhh_f, bih_b, bhh_b);

    proj_all_kernel<<<2610, 512>>>(word_emb, flag_emb, bound_emb, radical_emb, pinyin_emb);

    gather_kernel<<<Sn * Bn / 4, 128>>>(word_ids, flag_ids, bound_ids, radical_ids, pinyin_ids);

    dim3 lgrid(128, 2);
    lstm_kernel<<<lgrid, 256>>>(Whh_f, Whh_b, h0, c0);

    feats_kernel<<<Sn * Bn / 128, 512>>>(Wout, bout);

    crf_kernel<<<Bn / 2, 32>>>(transitions, tags, (float*)d_out);
}

// round 17
// speedup vs baseline: 1.0316x; 1.0126x over previous
#include <cuda_runtime.h>
#include <cuda_fp16.h>
#include <cstdint>
#include <math.h>

#define Bn 256
#define Sn 512
#define Hn 64
#define En 330
#define Tn 16
#define Gn 256   // 4H
#define START_IX 14
#define STOP_IX 15
#define NROWS_TOTAL 20868
#define NPAIRS 165   // En/2 k-pairs across the concatenated segments

// ---- scratch (static device memory) ----
__device__ __align__(16) __half2 g_WT2[NPAIRS * 512];  // paired Wih^T fp16: (w_{2p}, w_{2p+1}) at col j
__device__ float g_bias[512];
__device__ __align__(16) __half g_proj[(size_t)NROWS_TOTAL * 512];  // projected tables ~21.4MB (fp16)
__device__ __align__(16) __half g_xp[2][(size_t)Sn * Bn * Gn];      // x-projections  2x67MB (fp16)
__device__ __align__(16) __half g_h[2][(size_t)Sn * Bn * Hn];       // lstm hidden    2x16.8MB (fp16)
__device__ float g_feats[(size_t)Sn * Bn * Tn];        // emissions         8.4MB

// ---- packed f32x2 helpers ----
__device__ __forceinline__ void fma2(unsigned long long& d, unsigned long long a,
                                     unsigned long long b) {
    asm("fma.rn.f32x2 %0, %1, %2, %0;" : "+l"(d) : "l"(a), "l"(b));
}
__device__ __forceinline__ unsigned long long pack2(float a, float b) {
    unsigned long long v;
    asm("mov.b64 %0, {%1,%2};" : "=l"(v) : "f"(a), "f"(b));
    return v;
}
__device__ __forceinline__ float2 unpack2(unsigned long long v) {
    float2 r;
    asm("mov.b64 {%0,%1}, %2;" : "=f"(r.x), "=f"(r.y) : "l"(v));
    return r;
}
__device__ __forceinline__ float tanhfast(float x) {
    float y;
    asm("tanh.approx.f32 %0, %1;" : "=f"(y) : "f"(x));
    return y;
}
__device__ __forceinline__ float sigfast(float x) {
    return fmaf(0.5f, tanhfast(0.5f * x), 0.5f);
}
// load 4 consecutive halves as float4 (8B vector load)
__device__ __forceinline__ float4 ld4h(const __half* p) {
    uint2 u = *(const uint2*)p;
    __half2 h0 = *reinterpret_cast<__half2*>(&u.x);
    __half2 h1 = *reinterpret_cast<__half2*>(&u.y);
    float2 a = __half22float2(h0), b = __half22float2(h1);
    return make_float4(a.x, a.y, b.x, b.y);
}
// store float4 as 4 consecutive halves (8B vector store)
__device__ __forceinline__ void st4h(__half* p, float4 v) {
    __half2 h0 = __floats2half2_rn(v.x, v.y);
    __half2 h1 = __floats2half2_rn(v.z, v.w);
    uint2 u;
    u.x = *reinterpret_cast<unsigned*>(&h0);
    u.y = *reinterpret_cast<unsigned*>(&h1);
    *(uint2*)p = u;
}

// ---- K0: build paired fp16 WT (k-pairs) and fold biases ----
__global__ void prep_kernel(const float* __restrict__ Wf, const float* __restrict__ Wb,
                            const float* __restrict__ bihf, const float* __restrict__ bhhf,
                            const float* __restrict__ bihb, const float* __restrict__ bhhb) {
    int idx = blockIdx.x * blockDim.x + threadIdx.x;
    if (idx < NPAIRS * 512) {
        int p = idx / 512, j = idx % 512;
        int c0 = 2 * p, c1 = 2 * p + 1;    // rows in concatenated E
        float w0, w1;
        if (j < 256) { w0 = Wf[j * En + c0]; w1 = Wf[j * En + c1]; }
        else         { w0 = Wb[(j - 256) * En + c0]; w1 = Wb[(j - 256) * En + c1]; }
        g_WT2[idx] = __floats2half2_rn(w0, w1);
    }
    if (idx < 512) {
        g_bias[idx] = (idx < 256) ? (bihf[idx] + bhhf[idx]) : (bihb[idx - 256] + bhhb[idx - 256]);
    }
}

// ---- K1: project ALL embedding tables into g_proj (fp16 out), 8 rows/block ----
// segpair offsets (in k-pairs): word 0, flag 50, bound 75, radical 100, pinyin 125
__global__ __launch_bounds__(512)
void proj_all_kernel(const float* __restrict__ word, const float* __restrict__ flag,
                     const float* __restrict__ bound, const float* __restrict__ radical,
                     const float* __restrict__ pinyin) {
    const int bb = blockIdx.x;
    const float* emb;
    int nrows, width, segpair, base, r0;
    if (bb < 2500)      { emb = word;    nrows = 20000; width = 100; segpair = 0;   base = 0;     r0 = bb * 8; }
    else if (bb < 2508) { emb = flag;    nrows = 60;    width = 50;  segpair = 50;  base = 20000; r0 = (bb - 2500) * 8; }
    else if (bb < 2509) { emb = bound;   nrows = 8;     width = 50;  segpair = 75;  base = 20060; r0 = 0; }
    else if (bb < 2547) { emb = radical; nrows = 300;   width = 50;  segpair = 100; base = 20068; r0 = (bb - 2509) * 8; }
    else                { emb = pinyin;  nrows = 500;   width = 80;  segpair = 125; base = 20368; r0 = (bb - 2547) * 8; }

    const int j = threadIdx.x;             // output column 0..511
    __shared__ __align__(16) float es[8][112];
    for (int i = threadIdx.x; i < 8 * width; i += 512) {
        int rr = i / width, kk = i % width;
        es[rr][kk] = (r0 + rr < nrows) ? emb[(size_t)(r0 + rr) * width + kk] : 0.f;
    }
    __syncthreads();

    unsigned long long acc[8] = {0ull, 0ull, 0ull, 0ull, 0ull, 0ull, 0ull, 0ull};
    const int hw = width >> 1;
    for (int kk = 0; kk < hw; kk++) {
        __half2 wh = g_WT2[(size_t)(segpair + kk) * 512 + j];
        float2 wf = __half22float2(wh);
        unsigned long long w2 = pack2(wf.x, wf.y);
#pragma unroll
        for (int r = 0; r < 8; r++) {
            unsigned long long h2 = *(const unsigned long long*)&es[r][2 * kk];
            fma2(acc[r], h2, w2);
        }
    }
#pragma unroll
    for (int r = 0; r < 8; r++) {
        if (r0 + r < nrows) {
            float2 u = unpack2(acc[r]);
            g_proj[(size_t)(base + r0 + r) * 512 + j] = __float2half(u.x + u.y);
        }
    }
}

// ---- K2: gather-sum fp16 tables -> fp16 xp, fp32 accumulate, 4 pos/block ----
__global__ __launch_bounds__(128)
void gather_kernel(const int* __restrict__ wi, const int* __restrict__ fi,
                   const int* __restrict__ bi, const int* __restrict__ ri,
                   const int* __restrict__ pi) {
    const int t = threadIdx.x;             // 0..127, each handles 4 columns
    const float4 bias4 = *(const float4*)(g_bias + 4 * t);
#pragma unroll
    for (int pos = 0; pos < 4; pos++) {
        const int sb = blockIdx.x * 4 + pos;   // sb = s*B + b
        const int s = sb >> 8, b = sb & 255;
        const int iw  = wi[b * Sn + s];
        const int ifl = fi[b * Sn + s];
        const int ib  = bi[b * Sn + s];
        const int ir  = ri[b * Sn + s];
        const int ip  = pi[b * Sn + s];
        float4 a0 = ld4h(g_proj + (size_t)iw * 512 + 4 * t);
        float4 a1 = ld4h(g_proj + (size_t)(20000 + ifl) * 512 + 4 * t);
        float4 a2 = ld4h(g_proj + (size_t)(20060 + ib) * 512 + 4 * t);
        float4 a3 = ld4h(g_proj + (size_t)(20068 + ir) * 512 + 4 * t);
        float4 a4 = ld4h(g_proj + (size_t)(20368 + ip) * 512 + 4 * t);
        float4 v = bias4;
        v.x += a0.x + a1.x + a2.x + a3.x + a4.x;
        v.y += a0.y + a1.y + a2.y + a3.y + a4.y;
        v.z += a0.z + a1.z + a2.z + a3.z + a4.z;
        v.w += a0.w + a1.w + a2.w + a3.w + a4.w;
        if (t < 64) st4h(g_xp[0] + (size_t)sb * Gn + 4 * t, v);
        else        st4h(g_xp[1] + (size_t)sb * Gn + 4 * t - 256, v);
    }
}

// ---- K3: recurrence. grid (128,2)=256 CTAs, 256 thr, Bc=2, 2 CTAs/SM ----
// 2-step-deep x prefetch: load for step t+2 issued while computing step t.
__global__ __launch_bounds__(256, 2)
void lstm_kernel(const float* __restrict__ Whh_f, const float* __restrict__ Whh_b,
                 const float* __restrict__ h0, const float* __restrict__ c0) {
    const int dir = blockIdx.y;
    const int b0 = blockIdx.x * 2;
    const float* __restrict__ Whh = dir ? Whh_b : Whh_f;
    const __half* __restrict__ xp = g_xp[dir];
    __half* __restrict__ hout = g_h[dir];
    const int j = threadIdx.x;             // gate-output index 0..255

    unsigned long long wp[32];
    {
        const ulonglong2* wrow = (const ulonglong2*)(Whh + j * 64);
#pragma unroll
        for (int q = 0; q < 16; q++) { ulonglong2 t2 = wrow[q]; wp[2 * q] = t2.x; wp[2 * q + 1] = t2.y; }
    }

    __shared__ __align__(16) float h_sh[2][64];
    __shared__ float z_sh[2][256];

    const int cb = (j >> 6) & 1, ck = j & 63;
    float c = 0.f;
    if (j < 128) {
        c = c0[dir * Bn * Hn + (b0 + cb) * Hn + ck];
        h_sh[cb][ck] = h0[dir * Bn * Hn + (b0 + cb) * Hn + ck];
    }

    const int tstep = dir ? -1 : 1;
    int t = dir ? (Sn - 1) : 0;
    // prologue: x for step 0 and step 1
    float xc0, xc1, xn0, xn1;
    {
        const __half* x0r = xp + ((size_t)t * Bn + b0) * Gn + j;
        xc0 = __half2float(x0r[0]); xc1 = __half2float(x0r[Gn]);
        const __half* x1r = xp + ((size_t)(t + tstep) * Bn + b0) * Gn + j;
        xn0 = __half2float(x1r[0]); xn1 = __half2float(x1r[Gn]);
    }
    __syncthreads();

    for (int step = 0; step < Sn; step++) {
        // issue load for step t+2 (2-deep pipeline)
        float x20 = 0.f, x21 = 0.f;
        if (step + 2 < Sn) {
            const __half* x2r = xp + ((size_t)(t + 2 * tstep) * Bn + b0) * Gn + j;
            x20 = __half2float(x2r[0]); x21 = __half2float(x2r[Gn]);
        }
        unsigned long long acc0 = 0ull, acc1 = 0ull;
        const ulonglong2* h0p = (const ulonglong2*)h_sh[0];
        const ulonglong2* h1p = (const ulonglong2*)h_sh[1];
#pragma unroll
        for (int q = 0; q < 16; q++) {
            ulonglong2 v0 = h0p[q], v1 = h1p[q];
            fma2(acc0, v0.x, wp[2 * q]); fma2(acc0, v0.y, wp[2 * q + 1]);
            fma2(acc1, v1.x, wp[2 * q]); fma2(acc1, v1.y, wp[2 * q + 1]);
        }
        {
            float2 u0 = unpack2(acc0), u1 = unpack2(acc1);
            z_sh[0][j] = xc0 + u0.x + u0.y;
            z_sh[1][j] = xc1 + u1.x + u1.y;
        }
        __syncthreads();

        if (j < 128) {
            float zi = z_sh[cb][ck];
            float zf = z_sh[cb][64 + ck];
            float zg = z_sh[cb][128 + ck];
            float zo = z_sh[cb][192 + ck];
            c = sigfast(zf) * c + sigfast(zi) * tanhfast(zg);
            float hh = sigfast(zo) * tanhfast(c);
            h_sh[cb][ck] = hh;
            hout[((size_t)t * Bn + b0 + cb) * Hn + ck] = __float2half(hh);
        }
        __syncthreads();

        xc0 = xn0; xc1 = xn1;
        xn0 = x20; xn1 = x21;
        t += tstep;
    }
}

// ---- K4: emissions from fp16 h; 128 positions per block (4 tiles of 32),
//      Wout staged once per block ----
__global__ __launch_bounds__(512)
void feats_kernel(const float* __restrict__ Wout, const float* __restrict__ bout) {
    const int tid = threadIdx.x;
    __shared__ __align__(16) float hs[32][132];
    __shared__ __align__(16) float ws[16 * 132];
    __shared__ float bs[16];

    {
        int f = tid * 4;
        if (f < 2048) {
            float4 w4 = *(const float4*)(Wout + f);
            int row = f >> 7, off = f & 127;
            *(float4*)&ws[row * 132 + off] = w4;
        }
        if (tid < 16) bs[tid] = bout[tid];
    }

#pragma unroll
    for (int tile = 0; tile < 4; tile++) {
        const int p0 = blockIdx.x * 128 + tile * 32;
        __syncthreads();   // ws ready (tile 0) / previous tile's reads done
        {
            int f = tid * 4;
            float4 hf4 = ld4h(g_h[0] + (size_t)p0 * Hn + f);
            float4 hb4 = ld4h(g_h[1] + (size_t)p0 * Hn + f);
            int pos = f >> 6, off = f & 63;
            *(float4*)&hs[pos][off] = hf4;
            *(float4*)&hs[pos][64 + off] = hb4;
        }
        __syncthreads();

        const int pos = tid >> 4, tag = tid & 15;
        const float4* hv = (const float4*)&hs[pos][0];
        const float4* wv = (const float4*)&ws[tag * 132];
        float acc0 = bs[tag], acc1 = 0.f;
#pragma unroll
        for (int kq = 0; kq < 32; kq += 2) {
            float4 a = hv[kq], b = wv[kq];
            float4 a2 = hv[kq + 1], b2 = wv[kq + 1];
            acc0 = fmaf(a.x, b.x, fmaf(a.y, b.y, acc0));
            acc1 = fmaf(a.z, b.z, fmaf(a.w, b.w, acc1));
            acc0 = fmaf(a2.x, b2.x, fmaf(a2.y, b2.y, acc0));
            acc1 = fmaf(a2.z, b2.z, fmaf(a2.w, b2.w, acc1));
        }
        g_feats[(size_t)(p0 + pos) * Tn + tag] = acc0 + acc1;
    }
}

// ---- K5: CRF forward + real path -> loss. 3-deep feat prefetch ----
__global__ __launch_bounds__(32)
void crf_kernel(const float* __restrict__ transitions,
                const int* __restrict__ tags, float* __restrict__ out) {
    const int b = blockIdx.x * 2 + (threadIdx.x >> 4);
    const int n = threadIdx.x & 15;        // "next" tag this lane owns
    const unsigned FULL = 0xFFFFFFFFu;

    float expT[16];
#pragma unroll
    for (int k = 0; k < 16; k++) expT[k] = __expf(transitions[n * 16 + k]);

    // step 0 analytic: alpha = feats[0] + T[n, START]  (exact in fp32)
    float alpha = g_feats[(size_t)b * Tn + n] + transitions[n * 16 + START_IX];
    // 3-deep pipeline of feat loads (feat for s = 1, 2, 3)
    float fA = g_feats[((size_t)1 * Bn + b) * Tn + n];
    float fB = g_feats[((size_t)2 * Bn + b) * Tn + n];
    float fC = g_feats[((size_t)3 * Bn + b) * Tn + n];

    for (int s = 1; s < Sn; s++) {
        float fD = 0.f;
        if (s + 3 < Sn) fD = g_feats[((size_t)(s + 3) * Bn + b) * Tn + n];
        float m = __shfl_sync(FULL, alpha, 0, 16);
        float e = __expf(alpha - m);
        float acc_a = 0.f, acc_b = 0.f;
#pragma unroll
        for (int k = 0; k < 16; k += 2) {
            acc_a = fmaf(__shfl_sync(FULL, e, k, 16), expT[k], acc_a);
            acc_b = fmaf(__shfl_sync(FULL, e, k + 1, 16), expT[k + 1], acc_b);
        }
        alpha = fA + m + __logf(acc_a + acc_b);
        fA = fB; fB = fC; fC = fD;
    }
    float v = alpha + transitions[STOP_IX * 16 + n];
    float m2 = v;
#pragma unroll
    for (int o = 8; o; o >>= 1) m2 = fmaxf(m2, __shfl_xor_sync(FULL, m2, o, 16));
    float se = __expf(v - m2);
#pragma unroll
    for (int o = 8; o; o >>= 1) se += __shfl_xor_sync(FULL, se, o, 16);
    float all_sc = m2 + __logf(se);

    float rp = 0.f;
    for (int s = n; s < Sn; s += 16) {
        int tg = tags[b * Sn + s];
        int pv = (s == 0) ? START_IX : tags[b * Sn + s - 1];
        rp += g_feats[((size_t)s * Bn + b) * Tn + tg] + transitions[tg * 16 + pv];
    }
#pragma unroll
    for (int o = 8; o; o >>= 1) rp += __shfl_xor_sync(FULL, rp, o, 16);

    if (n == 0) {
        float real = rp + transitions[STOP_IX * 16 + tags[b * Sn + Sn - 1]];
        out[b] = all_sc - real;
    }
}

extern "C" void kernel_launch(void* const* d_in, const int* in_sizes, int n_in,
                              void* d_out, int out_size) {
    const float* word_emb    = (const float*)d_in[0];
    const float* flag_emb    = (const float*)d_in[1];
    const float* bound_emb   = (const float*)d_in[2];
    const float* radical_emb = (const float*)d_in[3];
    const float* pinyin_emb  = (const float*)d_in[4];
    const float* Wih_f = (const float*)d_in[5];
    const float* Whh_f = (const float*)d_in[6];
    const float* bih_f = (const float*)d_in[7];
    const float* bhh_f = (const float*)d_in[8];
    const float* Wih_b = (const float*)d_in[9];
    const float* Whh_b = (const float*)d_in[10];
    const float* bih_b = (const float*)d_in[11];
    const float* bhh_b = (const float*)d_in[12];
    const float* Wout  = (const float*)d_in[13];
    const float* bout  = (const float*)d_in[14];
    const float* transitions = (const float*)d_in[15];
    const float* h0 = (const float*)d_in[16];
    const float* c0 = (const float*)d_in[17];
    const int* word_ids    = (const int*)d_in[18];
    const int* flag_ids    = (const int*)d_in[19];
    const int* bound_ids   = (const int*)d_in[20];
    const int* radical_ids = (const int*)d_in[21];
    const int* pinyin_ids  = (const int*)d_in[22];
    const int* tags        = (const int*)d_in[23];

    prep_kernel<<<(NPAIRS * 512 + 255) / 256, 256>>>(Wih_f, Wih_b, bih_f, bhh_f, bih_b, bhh_b);

    proj_all_kernel<<<2610, 512>>>(word_emb, flag_emb, bound_emb, radical_emb, pinyin_emb);

    gather_kernel<<<Sn * Bn / 4, 128>>>(word_ids, flag_ids, bound_ids, radical_ids, pinyin_ids);

    dim3 lgrid(128, 2);
    lstm_kernel<<<lgrid, 256>>>(Whh_f, Whh_b, h0, c0);

    feats_kernel<<<Sn * Bn / 128, 512>>>(Wout, bout);

    crf_kernel<<<Bn / 2, 32>>>(transitions, tags, (float*)d_out);
}